// round 1
// baseline (speedup 1.0000x reference)
#include <cuda_runtime.h>
#include <math.h>

#define NMAX 50000
#define KEFF 265          // 256 radial + 9 local-frame cols (8 zero cols of W dropped)
#define DOUT 64
#define OSTRIDE 76
#define WARPS_PER_BLOCK 8
#define PWS 1216          // per-warp shared floats: rad(1060) + ar(64) + ac(64) + M(16) + pad

__device__ float g_lf[NMAX * 9];
__device__ float g_pooled[NMAX * 3];
__device__ float g_cnt[NMAX];

// ---------------------------------------------------------------------------
__global__ void zero_kernel(float* out, int out_n, int n_nodes) {
    int i = blockIdx.x * blockDim.x + threadIdx.x;
    int stride = gridDim.x * blockDim.x;
    for (int k = i; k < out_n; k += stride) out[k] = 0.f;
    for (int k = i; k < n_nodes; k += stride) g_cnt[k] = 0.f;
}

// ---------------------------------------------------------------------------
// Per-node: local frames + masked pooled coordinate.
__global__ void node_kernel(const float* __restrict__ coord,
                            const float* __restrict__ cw, int n) {
    int v = blockIdx.x * blockDim.x + threadIdx.x;
    if (v >= n) return;
    const float* cp = coord + v * 12;
    float cax = cp[0], cay = cp[1], caz = cp[2];
    float ccx = cp[3], ccy = cp[4], ccz = cp[5];
    float nnx = cp[6], nny = cp[7], nnz = cp[8];

    float xx = ccx - cax, xy = ccy - cay, xz = ccz - caz;
    float xn = sqrtf(xx * xx + xy * xy + xz * xz) + 1e-8f;
    xx /= xn; xy /= xn; xz /= xn;

    float tx = nnx - cax, ty = nny - cay, tz = nnz - caz;
    float d = tx * xx + ty * xy + tz * xz;
    float yx = tx - d * xx, yy = ty - d * xy, yz = tz - d * xz;
    float yn = sqrtf(yx * yx + yy * yy + yz * yz) + 1e-8f;
    yx /= yn; yy /= yn; yz /= yn;

    float zx = xy * yz - xz * yy;
    float zy = xz * yx - xx * yz;
    float zz = xx * yy - xy * yx;

    float* L = g_lf + v * 9;      // stack([x,y,z],axis=-1).reshape(9)
    L[0] = xx; L[1] = yx; L[2] = zx;
    L[3] = xy; L[4] = yy; L[5] = zy;
    L[6] = xz; L[7] = yz; L[8] = zz;

    float px = 0.f, py = 0.f, pz = 0.f, cs = 0.f;
#pragma unroll
    for (int i = 0; i < 4; i++) {
        float m = (cw[v * 4 + i] != 0.f) ? 1.f : 0.f;
        cs += m;
        px += cp[i * 3 + 0] * m;
        py += cp[i * 3 + 1] * m;
        pz += cp[i * 3 + 2] * m;
    }
    g_pooled[v * 3 + 0] = px / cs;   // ref does not clip csum
    g_pooled[v * 3 + 1] = py / cs;
    g_pooled[v * 3 + 2] = pz / cs;
}

// ---------------------------------------------------------------------------
// Edge kernel: one warp handles a group of 4 edges.
// Phase 1 (per edge): stage attr_r/attr_c/M in per-warp smem, compute the
//   256-entry radial (8 entries/lane) + edge_lf, write interleaved into
//   rad[k][4] (float4 rows), warp-reduce sum of squares -> rinv.
// Phase 2 (4 edges at once): y = Wt[265][64] x rad; each lane owns 2 outputs
//   x 4 edges: per k -> 1 broadcast LDS.128 + 1 LDS.64 + 8 FFMA.  FFMA-bound.
__global__ void __launch_bounds__(256, 2)
edge_kernel(const float* __restrict__ coord,
            const float* __restrict__ attr,
            const float* __restrict__ cw,
            const float* __restrict__ W,
            const float* __restrict__ bias,
            const int* __restrict__ row,
            const int* __restrict__ col,
            float* __restrict__ out, int E) {
    extern __shared__ float smem[];
    float* sW = smem;                       // KEFF*DOUT, layout [k][o]
    int tid = threadIdx.x;

    // Load W transposed into shared, dropping the 8 always-zero geo columns.
    for (int idx = tid; idx < KEFF * DOUT; idx += blockDim.x) {
        int k = idx >> 6, o = idx & 63;
        int ks = (k < 256) ? k : k + 8;     // cols 256..263 of W multiply zeros
        sW[idx] = W[o * 273 + ks];
    }
    __syncthreads();

    int warp = tid >> 5, lane = tid & 31;
    float* pw    = smem + KEFF * DOUT + warp * PWS;
    float* s_rad = pw;                      // KEFF*4 (interleaved by edge)
    float* s_ar  = pw + 1060;               // 64
    float* s_ac  = pw + 1124;               // 64
    float* s_M   = pw + 1188;               // 16

    int gwarp = blockIdx.x * WARPS_PER_BLOCK + warp;
    int nwarps = gridDim.x * WARPS_PER_BLOCK;
    int ngroups = (E + 3) >> 2;
    int b16 = lane & 15, half = lane >> 4;

    for (int g = gwarp; g < ngroups; g += nwarps) {
        int e0 = g * 4;
        float rinv[4];
        int rows[4], cols[4];

#pragma unroll
        for (int t = 0; t < 4; t++) {
            int e = e0 + t;
            if (e >= E) { rows[t] = -1; cols[t] = 0; rinv[t] = 0.f; continue; }
            int r = __ldg(row + e), c = __ldg(col + e);
            rows[t] = r; cols[t] = c;

            s_ar[lane]      = __ldg(attr + r * 64 + lane);
            s_ar[lane + 32] = __ldg(attr + r * 64 + 32 + lane);
            s_ac[lane]      = __ldg(attr + c * 64 + lane);
            s_ac[lane + 32] = __ldg(attr + c * 64 + 32 + lane);
            if (lane < 16) {
                int i = lane >> 2, j = lane & 3;
                float dx = __ldg(coord + r * 12 + i * 3 + 0) - __ldg(coord + c * 12 + j * 3 + 0);
                float dy = __ldg(coord + r * 12 + i * 3 + 1) - __ldg(coord + c * 12 + j * 3 + 1);
                float dz = __ldg(coord + r * 12 + i * 3 + 2) - __ldg(coord + c * 12 + j * 3 + 2);
                s_M[lane] = sqrtf(dx * dx + dy * dy + dz * dz)
                          * __ldg(cw + r * 4 + i) * __ldg(cw + c * 4 + j);
            }
            __syncwarp();

            // tmp_i(b) = sum_j M[i][j] * attr_c[j][b]
            float a0 = s_ac[b16], a1 = s_ac[16 + b16], a2 = s_ac[32 + b16], a3 = s_ac[48 + b16];
            float tmp0 = s_M[0]  * a0 + s_M[1]  * a1 + s_M[2]  * a2 + s_M[3]  * a3;
            float tmp1 = s_M[4]  * a0 + s_M[5]  * a1 + s_M[6]  * a2 + s_M[7]  * a3;
            float tmp2 = s_M[8]  * a0 + s_M[9]  * a1 + s_M[10] * a2 + s_M[11] * a3;
            float tmp3 = s_M[12] * a0 + s_M[13] * a1 + s_M[14] * a2 + s_M[15] * a3;

            float ssq = 0.f;
#pragma unroll
            for (int s = 0; s < 8; s++) {
                int a = half * 8 + s;
                float v = s_ar[a] * tmp0 + s_ar[16 + a] * tmp1
                        + s_ar[32 + a] * tmp2 + s_ar[48 + a] * tmp3;
                s_rad[(a * 16 + b16) * 4 + t] = v;
                ssq += v * v;
            }
            if (lane < 9) {
                float v = g_lf[r * 9 + lane] + g_lf[c * 9 + lane];
                s_rad[(256 + lane) * 4 + t] = v;
                ssq += v * v;
            }
#pragma unroll
            for (int off = 16; off; off >>= 1)
                ssq += __shfl_xor_sync(0xffffffffu, ssq, off);
            rinv[t] = 1.f / (sqrtf(ssq) + 1.f);
            __syncwarp();
        }

        // ---- matvec: 4 edges x 64 outputs, 2 outputs per lane ----
        float acc00 = 0.f, acc01 = 0.f, acc02 = 0.f, acc03 = 0.f;
        float acc10 = 0.f, acc11 = 0.f, acc12 = 0.f, acc13 = 0.f;
        const float4* rad4 = (const float4*)s_rad;
        const float2* w2 = ((const float2*)sW) + lane;
#pragma unroll 5
        for (int k = 0; k < KEFF; k++) {
            float4 rv = rad4[k];
            float2 w = w2[k * 32];
            acc00 += w.x * rv.x; acc01 += w.x * rv.y;
            acc02 += w.x * rv.z; acc03 += w.x * rv.w;
            acc10 += w.y * rv.x; acc11 += w.y * rv.y;
            acc12 += w.y * rv.z; acc13 += w.y * rv.w;
        }
        int o0 = lane * 2, o1 = lane * 2 + 1;
        float b0 = __ldg(bias + o0), b1 = __ldg(bias + o1);
        float a0[4] = {acc00, acc01, acc02, acc03};
        float a1[4] = {acc10, acc11, acc12, acc13};
#pragma unroll
        for (int t = 0; t < 4; t++) {
            if (rows[t] < 0) continue;
            float* ob = out + rows[t] * OSTRIDE;
            atomicAdd(ob + o0, (a0[t] + b0) * rinv[t]);
            atomicAdd(ob + o1, (a1[t] + b1) * rinv[t]);
        }
        // ---- coord aggregation + edge count ----
#pragma unroll
        for (int t = 0; t < 4; t++) {
            if (rows[t] < 0) continue;
            int r = rows[t], c = cols[t];
            if (lane < 12) {
                int comp = lane % 3;
                float v = __ldg(coord + r * 12 + lane) - g_pooled[c * 3 + comp];
                atomicAdd(out + r * OSTRIDE + 64 + lane, v);
            } else if (lane == 12) {
                atomicAdd(&g_cnt[r], 1.f);
            }
        }
    }
}

// ---------------------------------------------------------------------------
__global__ void finalize_kernel(float* out, int n) {
    int v = blockIdx.x * blockDim.x + threadIdx.x;
    if (v >= n) return;
    float cf = 1.f / fmaxf(g_cnt[v], 1.f);
    float* p = out + v * OSTRIDE + 64;
#pragma unroll
    for (int d = 0; d < 12; d++) p[d] *= cf;
}

// ---------------------------------------------------------------------------
extern "C" void kernel_launch(void* const* d_in, const int* in_sizes, int n_in,
                              void* d_out, int out_size) {
    const float* coord = (const float*)d_in[0];
    const float* attr  = (const float*)d_in[1];
    const float* cw    = (const float*)d_in[2];
    const float* W     = (const float*)d_in[3];
    const float* bias  = (const float*)d_in[4];
    const int*   row   = (const int*)d_in[5];
    const int*   col   = (const int*)d_in[6];
    float* out = (float*)d_out;

    int N = in_sizes[2] / 4;   // channel_weights is (N, 4)
    int E = in_sizes[5];

    int smem_bytes = (KEFF * DOUT + WARPS_PER_BLOCK * PWS) * sizeof(float);
    cudaFuncSetAttribute(edge_kernel, cudaFuncAttributeMaxDynamicSharedMemorySize,
                         smem_bytes);

    zero_kernel<<<512, 256>>>(out, out_size, N);
    node_kernel<<<(N + 255) / 256, 256>>>(coord, cw, N);
    edge_kernel<<<296, 256, smem_bytes>>>(coord, attr, cw, W, bias, row, col, out, E);
    finalize_kernel<<<(N + 255) / 256, 256>>>(out, N);
}

// round 2
// speedup vs baseline: 1.2004x; 1.2004x over previous
#include <cuda_runtime.h>
#include <math.h>
#include <stdint.h>

#define NMAX 50000
#define DOUT 64
#define OSTRIDE 76
#define KCH 34            // 34 k-chunks of 8 -> K = 272 (265 real + 7 zero pad)
#define KP 276            // rad row stride in floats (bank-conflict-free)
#define WOP 72            // sW row stride in floats (bank-conflict-free)
#define TILE_E 128

// shared memory offsets (floats)
#define OFF_W 0                     // 272*72      = 19584
#define OFF_RAD 19584               // 128*276     = 35328
#define OFF_ATT 54912               // 8 warps*256 =  2048
#define OFF_M 56960                 // 8 warps*16  =   128
#define OFF_RINV 57088              // 128
#define OFF_ROW 57216               // 128
#define OFF_BIAS 57344              // 64
#define SMEM_FLOATS 57408           // *4 = 229632 bytes

__device__ float g_lf[NMAX * 9];
__device__ float g_pooled[NMAX * 3];
__device__ float g_cnt[NMAX];

// ---------------------------------------------------------------------------
__global__ void zero_kernel(float* out, int out_n, int n_nodes) {
    int i = blockIdx.x * blockDim.x + threadIdx.x;
    int stride = gridDim.x * blockDim.x;
    for (int k = i; k < out_n; k += stride) out[k] = 0.f;
    for (int k = i; k < n_nodes; k += stride) g_cnt[k] = 0.f;
}

// ---------------------------------------------------------------------------
__global__ void node_kernel(const float* __restrict__ coord,
                            const float* __restrict__ cw, int n) {
    int v = blockIdx.x * blockDim.x + threadIdx.x;
    if (v >= n) return;
    const float* cp = coord + v * 12;
    float cax = cp[0], cay = cp[1], caz = cp[2];
    float ccx = cp[3], ccy = cp[4], ccz = cp[5];
    float nnx = cp[6], nny = cp[7], nnz = cp[8];

    float xx = ccx - cax, xy = ccy - cay, xz = ccz - caz;
    float xn = sqrtf(xx * xx + xy * xy + xz * xz) + 1e-8f;
    xx /= xn; xy /= xn; xz /= xn;

    float tx = nnx - cax, ty = nny - cay, tz = nnz - caz;
    float d = tx * xx + ty * xy + tz * xz;
    float yx = tx - d * xx, yy = ty - d * xy, yz = tz - d * xz;
    float yn = sqrtf(yx * yx + yy * yy + yz * yz) + 1e-8f;
    yx /= yn; yy /= yn; yz /= yn;

    float zx = xy * yz - xz * yy;
    float zy = xz * yx - xx * yz;
    float zz = xx * yy - xy * yx;

    float* L = g_lf + v * 9;
    L[0] = xx; L[1] = yx; L[2] = zx;
    L[3] = xy; L[4] = yy; L[5] = zy;
    L[6] = xz; L[7] = yz; L[8] = zz;

    float px = 0.f, py = 0.f, pz = 0.f, cs = 0.f;
#pragma unroll
    for (int i = 0; i < 4; i++) {
        float m = (cw[v * 4 + i] != 0.f) ? 1.f : 0.f;
        cs += m;
        px += cp[i * 3 + 0] * m;
        py += cp[i * 3 + 1] * m;
        pz += cp[i * 3 + 2] * m;
    }
    g_pooled[v * 3 + 0] = px / cs;
    g_pooled[v * 3 + 1] = py / cs;
    g_pooled[v * 3 + 2] = pz / cs;
}

// ---------------------------------------------------------------------------
__device__ __forceinline__ uint32_t f2tf(float f) {
    uint32_t u;
    asm("cvt.rna.tf32.f32 %0, %1;" : "=r"(u) : "f"(f));
    return u;
}

__device__ __forceinline__ void mma8(float& d0, float& d1, float& d2, float& d3,
                                     uint32_t a0, uint32_t a1, uint32_t a2, uint32_t a3,
                                     uint32_t b0, uint32_t b1) {
    asm volatile("mma.sync.aligned.m16n8k8.row.col.f32.tf32.tf32.f32 "
                 "{%0,%1,%2,%3}, {%4,%5,%6,%7}, {%8,%9}, {%0,%1,%2,%3};"
                 : "+f"(d0), "+f"(d1), "+f"(d2), "+f"(d3)
                 : "r"(a0), "r"(a1), "r"(a2), "r"(a3), "r"(b0), "r"(b1));
}

// Per-edge phase-1 body: build M via shuffles, compute radial + lf row of rad
// (tf32), the fp32 norm -> rinv, and the coord-diff atomics.
__device__ __forceinline__ void process_edge(
    int lane, int b16, int half, int eloc, int r, int c, float gv, float lfv,
    bool valid, const float* s_ar, float* sMW, uint32_t* sRad, float* sRinv,
    float* out)
{
    int i = (lane >> 2) & 3, j = lane & 3;
    float rx = __shfl_sync(0xffffffffu, gv, 3 * i);
    float ry = __shfl_sync(0xffffffffu, gv, 3 * i + 1);
    float rz = __shfl_sync(0xffffffffu, gv, 3 * i + 2);
    float cx = __shfl_sync(0xffffffffu, gv, 12 + 3 * j);
    float cy = __shfl_sync(0xffffffffu, gv, 13 + 3 * j);
    float cz = __shfl_sync(0xffffffffu, gv, 14 + 3 * j);
    float wr = __shfl_sync(0xffffffffu, gv, 24 + i);
    float wc = __shfl_sync(0xffffffffu, gv, 28 + j);
    if (lane < 16) {
        float dx = rx - cx, dy = ry - cy, dz = rz - cz;
        sMW[lane] = sqrtf(dx * dx + dy * dy + dz * dz) * wr * wc;
    }
    __syncwarp();

    const float* s_ac = s_ar + 64;
    float a0 = s_ac[b16], a1 = s_ac[16 + b16], a2 = s_ac[32 + b16], a3 = s_ac[48 + b16];
    float tmp0 = sMW[0]  * a0 + sMW[1]  * a1 + sMW[2]  * a2 + sMW[3]  * a3;
    float tmp1 = sMW[4]  * a0 + sMW[5]  * a1 + sMW[6]  * a2 + sMW[7]  * a3;
    float tmp2 = sMW[8]  * a0 + sMW[9]  * a1 + sMW[10] * a2 + sMW[11] * a3;
    float tmp3 = sMW[12] * a0 + sMW[13] * a1 + sMW[14] * a2 + sMW[15] * a3;

    uint32_t* rrow = sRad + eloc * KP;
    float ssq = 0.f;
#pragma unroll
    for (int s = 0; s < 8; s++) {
        int a = half * 8 + s;
        float v = s_ar[a] * tmp0 + s_ar[16 + a] * tmp1
                + s_ar[32 + a] * tmp2 + s_ar[48 + a] * tmp3;
        rrow[a * 16 + b16] = f2tf(v);
        ssq += v * v;
    }
    if (lane < 9) {
        rrow[256 + lane] = f2tf(lfv);
        ssq += lfv * lfv;
    } else if (lane < 20) {
        rrow[256 + lane] = 0u;   // k = 265..275 zero pad
    }
#pragma unroll
    for (int off = 16; off; off >>= 1)
        ssq += __shfl_xor_sync(0xffffffffu, ssq, off);
    if (lane == 0) sRinv[eloc] = 1.f / (sqrtf(ssq) + 1.f);

    if (valid) {
        if (lane < 12) {
            float pv = g_pooled[c * 3 + lane % 3];
            atomicAdd(out + r * OSTRIDE + 64 + lane, gv - pv);
        } else if (lane == 12) {
            atomicAdd(&g_cnt[r], 1.f);
        }
    }
    __syncwarp();
}

// ---------------------------------------------------------------------------
__global__ void __launch_bounds__(256, 1)
edge_kernel(const float* __restrict__ coord, const float* __restrict__ attr,
            const float* __restrict__ cw, const float* __restrict__ W,
            const float* __restrict__ bias, const int* __restrict__ row,
            const int* __restrict__ col, float* __restrict__ out, int E) {
    extern __shared__ float sm[];
    uint32_t* sW   = (uint32_t*)(sm + OFF_W);
    uint32_t* sRad = (uint32_t*)(sm + OFF_RAD);
    float* sAtt  = sm + OFF_ATT;
    float* sM    = sm + OFF_M;
    float* sRinv = sm + OFF_RINV;
    int*   sRow  = (int*)(sm + OFF_ROW);
    float* sBias = sm + OFF_BIAS;

    int tid = threadIdx.x, warp = tid >> 5, lane = tid & 31;

    // Stage W (tf32, transposed, geo-zero columns dropped) + bias. Once per CTA.
    for (int idx = tid; idx < 272 * 64; idx += 256) {
        int k = idx >> 6, o = idx & 63;
        float v = 0.f;
        if (k < 265) v = W[o * 273 + (k < 256 ? k : k + 8)];
        sW[k * WOP + o] = f2tf(v);
    }
    if (tid < 64) sBias[tid] = bias[tid];
    __syncthreads();

    const int g = lane >> 2, tig = lane & 3;
    const int b16 = lane & 15, half = lane >> 4;
    const int eh = (warp & 3) * 32;   // GEMM edge base (local)
    const int oh = (warp >> 2) * 32;  // GEMM output base
    float* sAttW = sAtt + warp * 256;
    float* sMW = sM + warp * 16;

    int ntile = (E + TILE_E - 1) / TILE_E;
    for (int tile = blockIdx.x; tile < ntile; tile += gridDim.x) {
        // ================= phase 1: build rad[128][276] =================
        int e0g = tile * TILE_E + warp * 16;
        int rc = 0;
        {
            int e = e0g + (lane & 15);
            if (e < E) rc = (lane < 16) ? row[e] : col[e];
        }
        if (lane < 16) sRow[warp * 16 + lane] = rc;

        for (int t = 0; t < 16; t += 2) {
            int r0 = __shfl_sync(0xffffffffu, rc, t);
            int c0 = __shfl_sync(0xffffffffu, rc, 16 + t);
            int r1 = __shfl_sync(0xffffffffu, rc, t + 1);
            int c1 = __shfl_sync(0xffffffffu, rc, 17 + t);

            int n0 = (lane < 16) ? r0 : c0;
            int n1 = (lane < 16) ? r1 : c1;
            float4 av0 = __ldg((const float4*)(attr + n0 * 64) + b16);
            float4 av1 = __ldg((const float4*)(attr + n1 * 64) + b16);

            auto gaddr = [&](int r, int c) -> const float* {
                if (lane < 12) return coord + r * 12 + lane;
                if (lane < 24) return coord + c * 12 + (lane - 12);
                if (lane < 28) return cw + r * 4 + (lane - 24);
                return cw + c * 4 + (lane - 28);
            };
            float gv0 = __ldg(gaddr(r0, c0));
            float gv1 = __ldg(gaddr(r1, c1));

            float lf0 = 0.f, lf1 = 0.f;
            if (lane < 9) {
                lf0 = g_lf[r0 * 9 + lane] + g_lf[c0 * 9 + lane];
                lf1 = g_lf[r1 * 9 + lane] + g_lf[c1 * 9 + lane];
            }

            ((float4*)sAttW)[lane] = av0;        // slot 0: [attr_r | attr_c]
            ((float4*)sAttW)[32 + lane] = av1;   // slot 1
            __syncwarp();

            process_edge(lane, b16, half, warp * 16 + t, r0, c0, gv0, lf0,
                         (e0g + t) < E, sAttW, sMW, sRad, sRinv, out);
            process_edge(lane, b16, half, warp * 16 + t + 1, r1, c1, gv1, lf1,
                         (e0g + t + 1) < E, sAttW + 128, sMW, sRad, sRinv, out);
        }
        __syncthreads();

        // ================= phase 2: tf32 MMA, 32 edges x 32 outs per warp ====
        float acc[2][4][4];
#pragma unroll
        for (int m = 0; m < 2; m++)
#pragma unroll
            for (int n = 0; n < 4; n++)
#pragma unroll
                for (int q = 0; q < 4; q++) acc[m][n][q] = 0.f;

        const uint32_t* aB0 = sRad + (eh + g) * KP + tig;
        const uint32_t* aB1 = sRad + (eh + 16 + g) * KP + tig;
        const uint32_t* bB  = sW + tig * WOP + oh + g;

#pragma unroll 2
        for (int kc = 0; kc < KCH; kc++) {
            int k0 = kc * 8;
            uint32_t A[2][4];
            A[0][0] = aB0[k0];
            A[0][1] = aB0[8 * KP + k0];
            A[0][2] = aB0[k0 + 4];
            A[0][3] = aB0[8 * KP + k0 + 4];
            A[1][0] = aB1[k0];
            A[1][1] = aB1[8 * KP + k0];
            A[1][2] = aB1[k0 + 4];
            A[1][3] = aB1[8 * KP + k0 + 4];
            uint32_t B[4][2];
#pragma unroll
            for (int n = 0; n < 4; n++) {
                B[n][0] = bB[k0 * WOP + n * 8];
                B[n][1] = bB[(k0 + 4) * WOP + n * 8];
            }
#pragma unroll
            for (int m = 0; m < 2; m++)
#pragma unroll
                for (int n = 0; n < 4; n++)
                    mma8(acc[m][n][0], acc[m][n][1], acc[m][n][2], acc[m][n][3],
                         A[m][0], A[m][1], A[m][2], A[m][3], B[n][0], B[n][1]);
        }

        // ================= epilogue: (acc + b) * rinv -> atomic scatter ======
#pragma unroll
        for (int m = 0; m < 2; m++) {
            int el0 = eh + m * 16 + g;
            int el1 = el0 + 8;
            bool v0 = (tile * TILE_E + el0) < E;
            bool v1 = (tile * TILE_E + el1) < E;
            float ri0 = sRinv[el0], ri1 = sRinv[el1];
            float* ob0 = out + sRow[el0] * OSTRIDE;
            float* ob1 = out + sRow[el1] * OSTRIDE;
#pragma unroll
            for (int n = 0; n < 4; n++) {
                int o = oh + n * 8 + 2 * tig;
                float bo0 = sBias[o], bo1 = sBias[o + 1];
                if (v0) {
                    atomicAdd(ob0 + o,     (acc[m][n][0] + bo0) * ri0);
                    atomicAdd(ob0 + o + 1, (acc[m][n][1] + bo1) * ri0);
                }
                if (v1) {
                    atomicAdd(ob1 + o,     (acc[m][n][2] + bo0) * ri1);
                    atomicAdd(ob1 + o + 1, (acc[m][n][3] + bo1) * ri1);
                }
            }
        }
        __syncthreads();   // protect rad/rinv/row before next tile's phase 1
    }
}

// ---------------------------------------------------------------------------
__global__ void finalize_kernel(float* out, int n) {
    int v = blockIdx.x * blockDim.x + threadIdx.x;
    if (v >= n) return;
    float cf = 1.f / fmaxf(g_cnt[v], 1.f);
    float* p = out + v * OSTRIDE + 64;
#pragma unroll
    for (int d = 0; d < 12; d++) p[d] *= cf;
}

// ---------------------------------------------------------------------------
extern "C" void kernel_launch(void* const* d_in, const int* in_sizes, int n_in,
                              void* d_out, int out_size) {
    const float* coord = (const float*)d_in[0];
    const float* attr  = (const float*)d_in[1];
    const float* cw    = (const float*)d_in[2];
    const float* W     = (const float*)d_in[3];
    const float* bias  = (const float*)d_in[4];
    const int*   row   = (const int*)d_in[5];
    const int*   col   = (const int*)d_in[6];
    float* out = (float*)d_out;

    int N = in_sizes[2] / 4;
    int E = in_sizes[5];

    int smem_bytes = SMEM_FLOATS * sizeof(float);   // 229632
    cudaFuncSetAttribute(edge_kernel, cudaFuncAttributeMaxDynamicSharedMemorySize,
                         smem_bytes);

    zero_kernel<<<512, 256>>>(out, out_size, N);
    node_kernel<<<(N + 255) / 256, 256>>>(coord, cw, N);
    edge_kernel<<<148, 256, smem_bytes>>>(coord, attr, cw, W, bias, row, col, out, E);
    finalize_kernel<<<(N + 255) / 256, 256>>>(out, N);
}